// round 13
// baseline (speedup 1.0000x reference)
#include <cuda_runtime.h>
#include <cstdint>

// Fixed shapes: B=1, N=64, X=256, Y=256, Z=32
#define NINST 64
#define V (256*256*32)                 // 2,097,152 floats / instance
#define WPI (V/32)                     // 65536 packed words / instance
#define G_TOT (((size_t)NINST*V)/128)  // 1,048,576 groups of 128 floats
#define GPI 16384                      // groups per instance
#define NSLICE (WPI/16)                // 4096 slices of 16 words
#define NTHR 256
#define NBLK 444                       // 148 SMs x 3 (all co-resident)
#define NSLOT 8

// Device state (zero-init at load; last block resets counters each launch;
// g_pk4 is fully rewritten every launch, so it never needs resetting).
__device__ uint4    g_pk4[G_TOT];      // 16 MB packed-bit mirror of the input
__device__ unsigned g_partial[NSLOT * NINST * NINST];
__device__ unsigned g_sync;
__device__ unsigned g_done;

// ---------------------------------------------------------------------------
// Pass 1 pack: group G = 128 consecutive floats. Lane L loads floats
// [128G+4L, 128G+4L+4); ballot c collects bit L for float 128G+4L+c.
// Word 4G+c therefore holds voxels {128G+4L+c}. V%128==0 -> groups never
// straddle instances and the permutation is identical for every instance,
// so pairwise popcounts and per-instance scores are exact.
// ---------------------------------------------------------------------------
__global__ __launch_bounds__(NTHR, 3) void fused_nms_kernel(
    const float* __restrict__ mask, float* __restrict__ out)
{
    __shared__ unsigned sm_pk[16][NINST];       //  4 KB slice staging
    __shared__ unsigned inter[NINST * NINST];   // 16 KB
    __shared__ unsigned ssc[NINST];
    __shared__ int s_done;

    const int tid  = threadIdx.x;
    const int lane = tid & 31;
    const int wp   = tid >> 5;                  // 8 warps

    // ======================= PASS 1: streaming pack =======================
    {
        const uint4* in4 = (const uint4*)mask;  // float bits; 1.0f != 0
        const long long g0 = ((long long)blockIdx.x * (long long)G_TOT) / NBLK;
        const long long g1 = ((long long)(blockIdx.x + 1) * (long long)G_TOT) / NBLK;

#define PACK(v, G)                                                        \
        {                                                                 \
            unsigned b0 = __ballot_sync(0xffffffffu, (v).x != 0u);        \
            unsigned b1 = __ballot_sync(0xffffffffu, (v).y != 0u);        \
            unsigned b2 = __ballot_sync(0xffffffffu, (v).z != 0u);        \
            unsigned b3 = __ballot_sync(0xffffffffu, (v).w != 0u);        \
            if (lane == 0) g_pk4[(G)] = make_uint4(b0, b1, b2, b3);       \
        }

        long long g = g0 + wp;                  // warp-interleaved groups
        for (; g + 24 < g1; g += 32) {          // unroll 4 (MLP)
            uint4 v0 = __ldcs(&in4[(size_t)(g)      * 32 + lane]);
            uint4 v1 = __ldcs(&in4[(size_t)(g + 8)  * 32 + lane]);
            uint4 v2 = __ldcs(&in4[(size_t)(g + 16) * 32 + lane]);
            uint4 v3 = __ldcs(&in4[(size_t)(g + 24) * 32 + lane]);
            PACK(v0, g) PACK(v1, g + 8) PACK(v2, g + 16) PACK(v3, g + 24)
        }
        for (; g < g1; g += 8) {
            uint4 v = __ldcs(&in4[(size_t)g * 32 + lane]);
            PACK(v, g)
        }
#undef PACK
    }

    // ===================== grid-wide sync (one wave) =====================
    __syncthreads();
    __threadfence();                            // publish g_pk4 writes
    if (tid == 0) {
        atomicAdd(&g_sync, 1u);
        while (atomicAdd(&g_sync, 0u) < NBLK) __nanosleep(64);
    }
    __syncthreads();
    __threadfence();                            // acquire

    // ================== PASS 2: pairwise popcount on bits ==================
    {
        // triangle decode (tid<240): off-diag tile k=tid>>1 (a<b),
        // words [8h,8h+8).  tid>=240: diag group d=tid-240 (scores).
        int i0 = 0, j0 = 4, w0 = 0, dg = -1;
        if (tid < 240) {
            int k = tid >> 1, a = 0, rem = k;
            while (rem >= 15 - a) { rem -= 15 - a; a++; }
            i0 = a * 4; j0 = (a + 1 + rem) * 4;
            w0 = (tid & 1) * 8;
        } else {
            dg = tid - 240;
        }
        unsigned acc[4][4];
#pragma unroll
        for (int r = 0; r < 4; r++)
#pragma unroll
            for (int c2 = 0; c2 < 4; c2++) acc[r][c2] = 0u;
        unsigned dacc[4] = {0u, 0u, 0u, 0u};

        const int s0 = (int)(((long long)blockIdx.x * NSLICE) / NBLK);
        const int s1 = (int)(((long long)(blockIdx.x + 1) * NSLICE) / NBLK);
        const int inst = tid & 63, q = tid >> 6;    // staging role

        for (int s = s0; s < s1; s++) {
            // slice s words [16s,16s+16): thread stages words [16s+4q, +4)
            // of its instance (one uint4, mostly L2-resident).
            uint4 w4 = __ldcg(&g_pk4[(size_t)inst * (WPI / 4) + s * 4 + q]);
            __syncthreads();                     // prior compute done
            sm_pk[4 * q + 0][inst] = w4.x;
            sm_pk[4 * q + 1][inst] = w4.y;
            sm_pk[4 * q + 2][inst] = w4.z;
            sm_pk[4 * q + 3][inst] = w4.w;
            __syncthreads();                     // staging visible

            if (tid < 240) {
#pragma unroll
                for (int w = 0; w < 8; w += 2) {
                    uint4 A0 = *(const uint4*)&sm_pk[w0 + w][i0];
                    uint4 B0 = *(const uint4*)&sm_pk[w0 + w][j0];
                    uint4 A1 = *(const uint4*)&sm_pk[w0 + w + 1][i0];
                    uint4 B1 = *(const uint4*)&sm_pk[w0 + w + 1][j0];
                    unsigned a0[4] = {A0.x, A0.y, A0.z, A0.w};
                    unsigned b0[4] = {B0.x, B0.y, B0.z, B0.w};
                    unsigned a1[4] = {A1.x, A1.y, A1.z, A1.w};
                    unsigned b1[4] = {B1.x, B1.y, B1.z, B1.w};
#pragma unroll
                    for (int r = 0; r < 4; r++)
#pragma unroll
                        for (int c2 = 0; c2 < 4; c2++)
                            acc[r][c2] += __popc(a0[r] & b0[c2]) +
                                          __popc(a1[r] & b1[c2]);
                }
            } else {
                // diag: score partials for instances [4dg, 4dg+4)
#pragma unroll
                for (int w = 0; w < 16; w++) {
#pragma unroll
                    for (int r = 0; r < 4; r++)
                        dacc[r] += __popc(sm_pk[w][4 * dg + r]);
                }
            }
        }

        // flush per-block totals (upper triangle + diagonal-as-score)
        unsigned* gp =
            g_partial + (unsigned)(blockIdx.x & (NSLOT - 1)) * (NINST * NINST);
        if (tid < 240) {
#pragma unroll
            for (int r = 0; r < 4; r++)
#pragma unroll
                for (int c2 = 0; c2 < 4; c2++)
                    atomicAdd(&gp[(i0 + r) * NINST + (j0 + c2)], acc[r][c2]);
        } else {
#pragma unroll
            for (int r = 0; r < 4; r++)
                atomicAdd(&gp[(4 * dg + r) * NINST + (4 * dg + r)], dacc[r]);
        }
    }

    // ===================== completion + fused tail =====================
    __threadfence();
    __syncthreads();
    if (tid == 0) s_done = (int)atomicAdd(&g_done, 1u);
    __syncthreads();
    if (s_done != NBLK - 1) return;

    {   // reduce NSLOT slots (L1-bypassing)
        const uint4* gp4 = (const uint4*)g_partial;
        uint4* in4s = (uint4*)inter;
        for (int e = tid; e < (NINST * NINST) / 4; e += NTHR) {
            uint4 s = make_uint4(0u, 0u, 0u, 0u);
#pragma unroll
            for (int k = 0; k < NSLOT; k++) {
                uint4 w = __ldcg(&gp4[k * (NINST * NINST / 4) + e]);
                s.x += w.x; s.y += w.y; s.z += w.z; s.w += w.w;
            }
            in4s[e] = s;
        }
    }
    __syncthreads();

    {   // symmetrize (lower-triangle tiles were never written -> max copy)
        for (int e = tid; e < NINST * NINST; e += NTHR) {
            int i = e >> 6, j = e & 63;
            if (i > j) {
                unsigned hi = inter[j * NINST + i];
                unsigned lo = inter[e];
                inter[e] = hi > lo ? hi : lo;
            }
        }
    }

    {   // reset device state for the next graph replay
        uint4 z = make_uint4(0u, 0u, 0u, 0u);
        uint4* gz = (uint4*)g_partial;
        for (int e = tid; e < (NSLOT * NINST * NINST) / 4; e += NTHR) gz[e] = z;
        if (tid == 0) { g_sync = 0u; g_done = 0u; }
    }

    if (tid < NINST) ssc[tid] = inter[tid * NINST + tid];  // score = diagonal
    __syncthreads();

    if (tid < 32) {
        const unsigned sj0 = ssc[lane];
        const unsigned sj1 = ssc[lane + 32];
        unsigned long long ind = ~0ULL;

        for (int i = 0; i < NINST; i++) {
            if (!((ind >> i) & 1ULL)) continue;   // warp-uniform
            const unsigned si  = ssc[i];
            const unsigned in0 = inter[i * NINST + lane];
            const unsigned in1 = inter[i * NINST + lane + 32];
            // iou > 0.5 <=> 2*inter > union (exact integers; counts < 2^23)
            const bool h0 = (2u * in0 > si + sj0 - in0);
            const bool h1 = (2u * in1 > si + sj1 - in1);
            unsigned a0 = __ballot_sync(0xffffffffu, h0 && (si > sj0));
            unsigned a1 = __ballot_sync(0xffffffffu, h1 && (si > sj1));
            unsigned c0m = __ballot_sync(0xffffffffu, h0 && (sj0 > si));
            unsigned c1m = __ballot_sync(0xffffffffu, h1 && (sj1 > si));
            unsigned long long A  = ((unsigned long long)a1 << 32) | a0;
            unsigned long long Bm = ((unsigned long long)c1m << 32) | c0m;
            if (A) {
                int jb = __ffsll((long long)A) - 1;    // first break j
                unsigned long long before = (1ULL << jb) - 1ULL;
                if (Bm & before) ind &= ~(1ULL << i);  // earlier j beat i
                ind &= ~(1ULL << jb);
            } else if (Bm) {
                ind &= ~(1ULL << i);
            }
        }
        out[lane]      = (float)((ind >> lane) & 1ULL);
        out[lane + 32] = (float)((ind >> (lane + 32)) & 1ULL);
    }
}

// ---------------------------------------------------------------------------
extern "C" void kernel_launch(void* const* d_in, const int* in_sizes, int n_in,
                              void* d_out, int out_size) {
    const float* mask = (const float*)d_in[0];
    fused_nms_kernel<<<NBLK, NTHR>>>(mask, (float*)d_out);
}

// round 14
// speedup vs baseline: 1.3339x; 1.3339x over previous
#include <cuda_runtime.h>
#include <cstdint>

// Fixed shapes: B=1, N=64, X=256, Y=256, Z=32
#define NINST 64
#define V (256*256*32)                 // 2,097,152 floats / instance
#define CHUNK_VOX 512                  // voxels per chunk per instance
#define CHUNK_BYTES (CHUNK_VOX*4)      // 2048 B per instance-slice
#define CHUNK_WORDS 16                 // packed words per chunk per instance
#define NCHUNK (V/CHUNK_VOX)           // 4096 chunks
#define GROUP 8                        // instances per TMA group / half
#define NG 8                           // groups per chunk (NINST/GROUP)
#define HALF_BYTES (GROUP*CHUNK_BYTES) // 16 KB per buffer half
#define NTHR 256
#define OCC 5                          // resident blocks per SM
#define NBLK (148*OCC)                 // 740
#define NSLOT 8                        // partial accumulator slots

// Dynamic smem layout
#define SM_RAW     0
#define SM_PACKED  (2*HALF_BYTES)                      // 32768
#define SM_MBAR    (SM_PACKED + CHUNK_WORDS*NINST*4)   // 36864
#define SM_CHUNK   (SM_MBAR + 16)                      // 36880
#define SM_TOTAL   36896

// Device state (zero-initialized at load; the last block of every launch
// restores it to zero, so graph replays start clean).
__device__ unsigned g_partial[NSLOT * NINST * NINST];
__device__ unsigned g_ticket;
__device__ unsigned g_done;

// ---------------------------------------------------------------------------
// PTX helpers
// ---------------------------------------------------------------------------
__device__ __forceinline__ unsigned su32(const void* p) {
    return (unsigned)__cvta_generic_to_shared(p);
}
__device__ __forceinline__ void mbar_init(unsigned a, unsigned cnt) {
    asm volatile("mbarrier.init.shared.b64 [%0], %1;" :: "r"(a), "r"(cnt) : "memory");
}
__device__ __forceinline__ void mbar_expect_tx(unsigned a, unsigned tx) {
    asm volatile("mbarrier.arrive.expect_tx.shared.b64 _, [%0], %1;"
                 :: "r"(a), "r"(tx) : "memory");
}
__device__ __forceinline__ void mbar_wait(unsigned a, unsigned parity) {
    asm volatile(
        "{\n\t.reg .pred p;\n\t"
        "WAIT_%=:\n\t"
        "mbarrier.try_wait.parity.acquire.cta.shared::cta.b64 p, [%0], %1, 0x989680;\n\t"
        "@!p bra WAIT_%=;\n\t}"
        :: "r"(a), "r"(parity) : "memory");
}
__device__ __forceinline__ void tma_bulk(unsigned dst, const void* src,
                                         unsigned bytes, unsigned mbar) {
    asm volatile(
        "cp.async.bulk.shared::cta.global.mbarrier::complete_tx::bytes [%0], [%1], %2, [%3];"
        :: "r"(dst), "l"(src), "r"(bytes), "r"(mbar) : "memory");
}
__device__ __forceinline__ void fence_async() {
    asm volatile("fence.proxy.async.shared::cta;" ::: "memory");
}

// ---------------------------------------------------------------------------
// Single fused kernel (Round-4 structure, 5 pipelines/SM):
// persistent TMA-fed pack + full 64x64 pairwise popcount; last block
// reduces, runs the exact-integer NMS, writes output, resets state.
// ---------------------------------------------------------------------------
extern __shared__ char smem[];

__global__ __launch_bounds__(NTHR, OCC) void fused_nms_kernel(
    const float* __restrict__ mask, float* __restrict__ out)
{
    const unsigned sbase = su32(smem);
    unsigned (*packed)[NINST] = (unsigned (*)[NINST])(smem + SM_PACKED);
    int* s_chunk = (int*)(smem + SM_CHUNK);
    const unsigned mb[2] = {sbase + SM_MBAR, sbase + SM_MBAR + 8};

    const int tid  = threadIdx.x;
    const int lane = tid & 31;
    const int wp   = tid >> 5;

    if (tid == 0) {
        mbar_init(mb[0], 1);
        mbar_init(mb[1], 1);
        fence_async();
    }

    // 16x16 pair-tile map (4x4 instance pairs / thread), bank-conflict free.
    const int ti = ((wp & 1) << 3) + (lane & 7);
    const int tj = ((wp >> 1) << 2) + (lane >> 3);
    const int i0 = ti * 4, j0 = tj * 4;

    unsigned acc[4][4];
#pragma unroll
    for (int r = 0; r < 4; r++)
#pragma unroll
        for (int c2 = 0; c2 < 4; c2++) acc[r][c2] = 0u;

    // tid0: issue one group (8 instances x 2KB) into buffer half hb.
    auto issue = [&](int g, int hb, int c) {
        const float* src = mask + (size_t)c * CHUNK_VOX + (size_t)(g * GROUP) * V;
        const unsigned dst = sbase + SM_RAW + hb * HALF_BYTES;
        mbar_expect_tx(mb[hb], HALF_BYTES);
#pragma unroll
        for (int jj = 0; jj < GROUP; jj++)
            tma_bulk(dst + jj * CHUNK_BYTES, src + (size_t)jj * V,
                     CHUNK_BYTES, mb[hb]);
    };

    // Prologue: first ticket + groups 0,1 in flight.
    if (tid == 0) {
        int t0 = (int)atomicAdd(&g_ticket, 1u);
        *s_chunk = t0;
        if (t0 < NCHUNK) { issue(0, 0, t0); issue(1, 1, t0); }
    }
    __syncthreads();
    int c = *s_chunk;

    // Pack read address: warp wp owns words 2wp,2wp+1; lane reads 2 voxels.
    const unsigned raw_rd = sbase + SM_RAW + (unsigned)(wp * 64 + lane * 2) * 4u;
    unsigned ph0 = 0, ph1 = 0;
    int nextc = NCHUNK;  // tid0-local

    while (c < NCHUNK) {
#pragma unroll
        for (int g = 0; g < NG; g++) {
            const int hb = g & 1;
            if (hb == 0) { mbar_wait(mb[0], ph0); ph0 ^= 1; }
            else         { mbar_wait(mb[1], ph1); ph1 ^= 1; }

            // Pack 8 instances (fixed even/odd voxel permutation; identical
            // for all instances, so pairwise popcounts are unaffected).
            const unsigned rbase = raw_rd + (unsigned)hb * HALF_BYTES;
#pragma unroll
            for (int jj = 0; jj < GROUP; jj++) {
                uint2 v;
                asm volatile("ld.shared.v2.u32 {%0,%1}, [%2];"
                             : "=r"(v.x), "=r"(v.y)
                             : "r"(rbase + (unsigned)jj * CHUNK_BYTES));
                unsigned b0 = __ballot_sync(0xffffffffu, v.x != 0u);
                unsigned b1 = __ballot_sync(0xffffffffu, v.y != 0u);
                if (lane == 0) {
                    const int j = g * GROUP + jj;
                    packed[wp * 2][j]     = b0;
                    packed[wp * 2 + 1][j] = b1;
                }
            }
            __syncthreads();  // half hb fully consumed; packed cols visible

            if (tid == 0) {
                fence_async();  // order generic reads before async refill
                if (g < NG - 2) {
                    issue(g + 2, hb, c);
                } else if (g == NG - 2) {
                    nextc = (int)atomicAdd(&g_ticket, 1u);
                    *s_chunk = nextc;   // published by next g's __syncthreads
                    if (nextc < NCHUNK) issue(0, 0, nextc);
                } else {
                    if (nextc < NCHUNK) issue(1, 1, nextc);
                }
            }
        }

        // Phase B: accumulate this chunk's 64x64 intersections in registers.
        // (overlaps the next chunk's TMA loads already in flight)
#pragma unroll
        for (int w = 0; w < CHUNK_WORDS; w += 2) {
            uint4 A0 = *(const uint4*)&packed[w][i0];
            uint4 B0 = *(const uint4*)&packed[w][j0];
            uint4 A1 = *(const uint4*)&packed[w + 1][i0];
            uint4 B1 = *(const uint4*)&packed[w + 1][j0];
            unsigned a0[4] = {A0.x, A0.y, A0.z, A0.w};
            unsigned b0[4] = {B0.x, B0.y, B0.z, B0.w};
            unsigned a1[4] = {A1.x, A1.y, A1.z, A1.w};
            unsigned b1[4] = {B1.x, B1.y, B1.z, B1.w};
#pragma unroll
            for (int r = 0; r < 4; r++)
#pragma unroll
                for (int c2 = 0; c2 < 4; c2++)
                    acc[r][c2] += __popc(a0[r] & b0[c2]) + __popc(a1[r] & b1[c2]);
        }
        __syncthreads();  // protect packed[] against next chunk's pack writes
        c = *s_chunk;
    }

    // Flush per-block totals (16 atomics / thread, NSLOT-way spread).
    {
        unsigned* gp =
            g_partial + (unsigned)(blockIdx.x & (NSLOT - 1)) * (NINST * NINST);
#pragma unroll
        for (int r = 0; r < 4; r++)
#pragma unroll
            for (int c2 = 0; c2 < 4; c2++)
                atomicAdd(&gp[(i0 + r) * NINST + (j0 + c2)], acc[r][c2]);
    }
    __threadfence();
    __syncthreads();
    if (tid == 0) *s_chunk = (int)atomicAdd(&g_done, 1u);
    __syncthreads();
    if (*s_chunk != NBLK - 1) return;

    // ------------------- Last block: reduce + NMS + reset -------------------
    unsigned* inter = (unsigned*)smem;             // 16 KB (raw area is dead)
    unsigned* ssc   = (unsigned*)(smem + 16384);

    {   // vectorized reduce of NSLOT slots (L1-bypassing loads)
        const uint4* gp4 = (const uint4*)g_partial;   // [NSLOT][1024] uint4
        uint4* in4 = (uint4*)inter;
        for (int e = tid; e < (NINST * NINST) / 4; e += NTHR) {
            uint4 s = make_uint4(0u, 0u, 0u, 0u);
#pragma unroll
            for (int k = 0; k < NSLOT; k++) {
                uint4 v = __ldcg(&gp4[k * (NINST * NINST / 4) + e]);
                s.x += v.x; s.y += v.y; s.z += v.z; s.w += v.w;
            }
            in4[e] = s;
        }
    }
    __syncthreads();

    {   // reset device state for the next replay
        uint4 z = make_uint4(0u, 0u, 0u, 0u);
        uint4* gz = (uint4*)g_partial;
        for (int e = tid; e < (NSLOT * NINST * NINST) / 4; e += NTHR) gz[e] = z;
        if (tid == 0) { g_ticket = 0u; g_done = 0u; }
    }

    if (tid < NINST) ssc[tid] = inter[tid * NINST + tid];  // score = diagonal
    __syncthreads();

    if (tid < 32) {
        const unsigned sj0 = ssc[lane];
        const unsigned sj1 = ssc[lane + 32];
        unsigned long long ind = ~0ULL;

        for (int i = 0; i < NINST; i++) {
            if (!((ind >> i) & 1ULL)) continue;  // warp-uniform
            const unsigned si  = ssc[i];
            const unsigned in0 = inter[i * NINST + lane];
            const unsigned in1 = inter[i * NINST + lane + 32];
            // iou > 0.5 <=> 2*inter > union (exact integers; counts < 2^23)
            const bool h0 = (2u * in0 > si + sj0 - in0);
            const bool h1 = (2u * in1 > si + sj1 - in1);
            unsigned a0 = __ballot_sync(0xffffffffu, h0 && (si > sj0));
            unsigned a1 = __ballot_sync(0xffffffffu, h1 && (si > sj1));
            unsigned c0 = __ballot_sync(0xffffffffu, h0 && (sj0 > si));
            unsigned c1 = __ballot_sync(0xffffffffu, h1 && (sj1 > si));
            unsigned long long A  = ((unsigned long long)a1 << 32) | a0;
            unsigned long long Bm = ((unsigned long long)c1 << 32) | c0;
            if (A) {
                int jb = __ffsll((long long)A) - 1;   // first break j
                unsigned long long before = (1ULL << jb) - 1ULL;
                if (Bm & before) ind &= ~(1ULL << i); // earlier j beat i first
                ind &= ~(1ULL << jb);
            } else if (Bm) {
                ind &= ~(1ULL << i);
            }
        }
        out[lane]      = (float)((ind >> lane) & 1ULL);
        out[lane + 32] = (float)((ind >> (lane + 32)) & 1ULL);
    }
}

// ---------------------------------------------------------------------------
extern "C" void kernel_launch(void* const* d_in, const int* in_sizes, int n_in,
                              void* d_out, int out_size) {
    const float* mask = (const float*)d_in[0];
    static bool attr_done = false;
    if (!attr_done) {  // host-side attrs: first (pre-capture) call sets them
        cudaFuncSetAttribute(fused_nms_kernel,
                             cudaFuncAttributeMaxDynamicSharedMemorySize,
                             SM_TOTAL);
        cudaFuncSetAttribute(fused_nms_kernel,
                             cudaFuncAttributePreferredSharedMemoryCarveout,
                             cudaSharedmemCarveoutMaxShared);
        attr_done = true;
    }
    fused_nms_kernel<<<NBLK, NTHR, SM_TOTAL>>>(mask, (float*)d_out);
}

// round 15
// speedup vs baseline: 1.4149x; 1.0607x over previous
#include <cuda_runtime.h>
#include <cstdint>

// Fixed shapes: B=1, N=64, X=256, Y=256, Z=32
#define NINST 64
#define V (256*256*32)                 // 2,097,152 floats / instance
#define CHUNK_VOX 512                  // voxels per chunk per instance
#define CHUNK_BYTES (CHUNK_VOX*4)      // 2048 B per bulk load
#define CHUNK_WORDS 16                 // packed words per chunk per instance
#define NCHUNK (V/CHUNK_VOX)           // 4096 chunks
#define GROUP 16                       // instances per TMA group / half
#define HALF_BYTES (GROUP*CHUNK_BYTES) // 32 KB per buffer half
#define NTHR 256
#define NBLK 444                       // 148 SMs * 3 resident blocks
#define NSLOT 8                        // partial accumulator slots
#define IMASK 0x0000ffffu              // issuing lanes (tid 0..15)

// Dynamic smem layout
#define SM_RAW     0
#define SM_PACKED  (2*HALF_BYTES)                      // 65536
#define SM_MBAR    (SM_PACKED + CHUNK_WORDS*NINST*4)   // 69632
#define SM_CHUNK   (SM_MBAR + 16)                      // 69648
#define SM_TOTAL   69664

// Device state (zero-initialized at load; the last block of every launch
// restores it to zero, so graph replays start clean).
__device__ unsigned g_partial[NSLOT * NINST * NINST];
__device__ unsigned g_ticket;
__device__ unsigned g_done;

// ---------------------------------------------------------------------------
// PTX helpers
// ---------------------------------------------------------------------------
__device__ __forceinline__ unsigned su32(const void* p) {
    return (unsigned)__cvta_generic_to_shared(p);
}
__device__ __forceinline__ void mbar_init(unsigned a, unsigned cnt) {
    asm volatile("mbarrier.init.shared.b64 [%0], %1;" :: "r"(a), "r"(cnt) : "memory");
}
__device__ __forceinline__ void mbar_expect_tx(unsigned a, unsigned tx) {
    asm volatile("mbarrier.arrive.expect_tx.shared.b64 _, [%0], %1;"
                 :: "r"(a), "r"(tx) : "memory");
}
__device__ __forceinline__ void mbar_wait(unsigned a, unsigned parity) {
    asm volatile(
        "{\n\t.reg .pred p;\n\t"
        "WAIT_%=:\n\t"
        "mbarrier.try_wait.parity.acquire.cta.shared::cta.b64 p, [%0], %1, 0x989680;\n\t"
        "@!p bra WAIT_%=;\n\t}"
        :: "r"(a), "r"(parity) : "memory");
}
__device__ __forceinline__ void tma_bulk(unsigned dst, const void* src,
                                         unsigned bytes, unsigned mbar) {
    asm volatile(
        "cp.async.bulk.shared::cta.global.mbarrier::complete_tx::bytes [%0], [%1], %2, [%3];"
        :: "r"(dst), "l"(src), "r"(bytes), "r"(mbar) : "memory");
}
__device__ __forceinline__ void fence_async() {
    asm volatile("fence.proxy.async.shared::cta;" ::: "memory");
}

// ---------------------------------------------------------------------------
// Single fused kernel: Round-4 champion structure (444x256, 2x32KB halves,
// 16-instance groups, FULL 64x64 phase B) with 16-lane TMA issue.
// Last block: reduce + exact-integer NMS + state reset.
// ---------------------------------------------------------------------------
extern __shared__ char smem[];

__global__ __launch_bounds__(NTHR) void fused_nms_kernel(
    const float* __restrict__ mask, float* __restrict__ out)
{
    const unsigned sbase = su32(smem);
    unsigned (*packed)[NINST] = (unsigned (*)[NINST])(smem + SM_PACKED);
    volatile int* s_chunk = (volatile int*)(smem + SM_CHUNK);
    const unsigned mb[2] = {sbase + SM_MBAR, sbase + SM_MBAR + 8};

    const int tid  = threadIdx.x;
    const int lane = tid & 31;
    const int wp   = tid >> 5;           // 8 warps

    if (tid == 0) {
        mbar_init(mb[0], 1);
        mbar_init(mb[1], 1);
        fence_async();
    }

    // 16x16 pair-tile map (4x4 instance pairs / thread), bank-conflict free.
    const int ti = ((wp & 1) << 3) + (lane & 7);
    const int tj = ((wp >> 1) << 2) + (lane >> 3);
    const int i0 = ti * 4, j0 = tj * 4;

    unsigned acc[4][4];
#pragma unroll
    for (int r = 0; r < 4; r++)
#pragma unroll
        for (int c2 = 0; c2 < 4; c2++) acc[r][c2] = 0u;

    // Lane jj (tid<16) fires one 2KB bulk for instance g*16+jj into half hb.
    auto lane_issue = [&](int g, int hb, int c) {
        const float* src =
            mask + (size_t)c * CHUNK_VOX + (size_t)(g * GROUP + tid) * V;
        tma_bulk(sbase + SM_RAW + hb * HALF_BYTES + tid * CHUNK_BYTES,
                 src, CHUNK_BYTES, mb[hb]);
    };

    // Prologue: first ticket, then groups 0,1 in flight (16-lane issue).
    if (tid == 0) *s_chunk = (int)atomicAdd(&g_ticket, 1u);
    __syncthreads();
    int c = *s_chunk;
    if (tid < 16 && c < NCHUNK) {
        if (tid == 0) {
            mbar_expect_tx(mb[0], HALF_BYTES);
            mbar_expect_tx(mb[1], HALF_BYTES);
        }
        __syncwarp(IMASK);
        lane_issue(0, 0, c);
        lane_issue(1, 1, c);
    }

    // Pack read address: warp wp owns words 2wp,2wp+1; lane reads 2 voxels.
    const unsigned raw_rd = sbase + SM_RAW + (unsigned)(wp * 64 + lane * 2) * 4u;
    unsigned ph0 = 0, ph1 = 0;
    int nextc = NCHUNK;   // issuing-lane local (set at g==2)

    while (c < NCHUNK) {
#pragma unroll
        for (int g = 0; g < 4; g++) {
            const int hb = g & 1;
            if (hb == 0) { mbar_wait(mb[0], ph0); ph0 ^= 1; }
            else         { mbar_wait(mb[1], ph1); ph1 ^= 1; }

            // Pack 16 instances (fixed even/odd voxel permutation; identical
            // for all instances, so pairwise popcounts are unaffected).
            const unsigned rbase = raw_rd + (unsigned)hb * HALF_BYTES;
#pragma unroll
            for (int jj = 0; jj < GROUP; jj++) {
                uint2 v;
                asm volatile("ld.shared.v2.u32 {%0,%1}, [%2];"
                             : "=r"(v.x), "=r"(v.y)
                             : "r"(rbase + (unsigned)jj * CHUNK_BYTES));
                unsigned b0 = __ballot_sync(0xffffffffu, v.x != 0u);
                unsigned b1 = __ballot_sync(0xffffffffu, v.y != 0u);
                if (lane == 0) {
                    const int j = g * GROUP + jj;
                    packed[wp * 2][j]     = b0;
                    packed[wp * 2 + 1][j] = b1;
                }
            }
            __syncthreads();  // half hb fully consumed; packed cols visible

            // Refill half hb (16-lane TMA issue).
            if (tid < 16) {
                fence_async();  // order generic LDS reads before async refill
                if (g == 0) {
                    if (tid == 0) mbar_expect_tx(mb[0], HALF_BYTES);
                    __syncwarp(IMASK);
                    lane_issue(2, 0, c);
                } else if (g == 1) {
                    if (tid == 0) mbar_expect_tx(mb[1], HALF_BYTES);
                    __syncwarp(IMASK);
                    lane_issue(3, 1, c);
                } else if (g == 2) {
                    if (tid == 0) *s_chunk = (int)atomicAdd(&g_ticket, 1u);
                    __syncwarp(IMASK);
                    nextc = *s_chunk;
                    if (nextc < NCHUNK) {
                        if (tid == 0) mbar_expect_tx(mb[0], HALF_BYTES);
                        __syncwarp(IMASK);
                        lane_issue(0, 0, nextc);
                    }
                } else {
                    if (nextc < NCHUNK) {
                        if (tid == 0) mbar_expect_tx(mb[1], HALF_BYTES);
                        __syncwarp(IMASK);
                        lane_issue(1, 1, nextc);
                    }
                }
            }
        }

        // Phase B: full 64x64 accumulation in registers (uniform work;
        // overlaps the next chunk's TMA loads already in flight).
#pragma unroll
        for (int w = 0; w < CHUNK_WORDS; w += 2) {
            uint4 A0 = *(const uint4*)&packed[w][i0];
            uint4 B0 = *(const uint4*)&packed[w][j0];
            uint4 A1 = *(const uint4*)&packed[w + 1][i0];
            uint4 B1 = *(const uint4*)&packed[w + 1][j0];
            unsigned a0[4] = {A0.x, A0.y, A0.z, A0.w};
            unsigned b0[4] = {B0.x, B0.y, B0.z, B0.w};
            unsigned a1[4] = {A1.x, A1.y, A1.z, A1.w};
            unsigned b1[4] = {B1.x, B1.y, B1.z, B1.w};
#pragma unroll
            for (int r = 0; r < 4; r++)
#pragma unroll
                for (int c2 = 0; c2 < 4; c2++)
                    acc[r][c2] += __popc(a0[r] & b0[c2]) + __popc(a1[r] & b1[c2]);
        }
        __syncthreads();  // protect packed[] against next chunk's pack writes
        c = *s_chunk;
    }

    // Flush per-block totals (16 atomics / thread, NSLOT-way spread).
    {
        unsigned* gp =
            g_partial + (unsigned)(blockIdx.x & (NSLOT - 1)) * (NINST * NINST);
#pragma unroll
        for (int r = 0; r < 4; r++)
#pragma unroll
            for (int c2 = 0; c2 < 4; c2++)
                atomicAdd(&gp[(i0 + r) * NINST + (j0 + c2)], acc[r][c2]);
    }
    __threadfence();
    __syncthreads();
    if (tid == 0) *s_chunk = (int)atomicAdd(&g_done, 1u);
    __syncthreads();
    if (*s_chunk != NBLK - 1) return;

    // ------------------- Last block: reduce + NMS + reset -------------------
    unsigned* inter = (unsigned*)smem;             // 16 KB (raw area is dead)
    unsigned* ssc   = (unsigned*)(smem + 16384);

    {   // vectorized reduce of NSLOT slots (L1-bypassing loads)
        const uint4* gp4 = (const uint4*)g_partial;   // [NSLOT][1024] uint4
        uint4* in4 = (uint4*)inter;
        for (int e = tid; e < (NINST * NINST) / 4; e += NTHR) {
            uint4 s = make_uint4(0u, 0u, 0u, 0u);
#pragma unroll
            for (int k = 0; k < NSLOT; k++) {
                uint4 v = __ldcg(&gp4[k * (NINST * NINST / 4) + e]);
                s.x += v.x; s.y += v.y; s.z += v.z; s.w += v.w;
            }
            in4[e] = s;
        }
    }
    __syncthreads();

    {   // reset device state for the next replay
        uint4 z = make_uint4(0u, 0u, 0u, 0u);
        uint4* gz = (uint4*)g_partial;
        for (int e = tid; e < (NSLOT * NINST * NINST) / 4; e += NTHR) gz[e] = z;
        if (tid == 0) { g_ticket = 0u; g_done = 0u; }
    }

    if (tid < NINST) ssc[tid] = inter[tid * NINST + tid];  // score = diagonal
    __syncthreads();

    if (tid < 32) {
        const unsigned sj0 = ssc[lane];
        const unsigned sj1 = ssc[lane + 32];
        unsigned long long ind = ~0ULL;

        for (int i = 0; i < NINST; i++) {
            if (!((ind >> i) & 1ULL)) continue;  // warp-uniform
            const unsigned si  = ssc[i];
            const unsigned in0 = inter[i * NINST + lane];
            const unsigned in1 = inter[i * NINST + lane + 32];
            // iou > 0.5 <=> 2*inter > union (exact integers; counts < 2^23)
            const bool h0 = (2u * in0 > si + sj0 - in0);
            const bool h1 = (2u * in1 > si + sj1 - in1);
            unsigned a0 = __ballot_sync(0xffffffffu, h0 && (si > sj0));
            unsigned a1 = __ballot_sync(0xffffffffu, h1 && (si > sj1));
            unsigned c0 = __ballot_sync(0xffffffffu, h0 && (sj0 > si));
            unsigned c1 = __ballot_sync(0xffffffffu, h1 && (sj1 > si));
            unsigned long long A  = ((unsigned long long)a1 << 32) | a0;
            unsigned long long Bm = ((unsigned long long)c1 << 32) | c0;
            if (A) {
                int jb = __ffsll((long long)A) - 1;   // first break j
                unsigned long long before = (1ULL << jb) - 1ULL;
                if (Bm & before) ind &= ~(1ULL << i); // earlier j beat i first
                ind &= ~(1ULL << jb);
            } else if (Bm) {
                ind &= ~(1ULL << i);
            }
        }
        out[lane]      = (float)((ind >> lane) & 1ULL);
        out[lane + 32] = (float)((ind >> (lane + 32)) & 1ULL);
    }
}

// ---------------------------------------------------------------------------
extern "C" void kernel_launch(void* const* d_in, const int* in_sizes, int n_in,
                              void* d_out, int out_size) {
    const float* mask = (const float*)d_in[0];
    static bool attr_done = false;
    if (!attr_done) {  // host-side attrs: first (pre-capture) call sets them
        cudaFuncSetAttribute(fused_nms_kernel,
                             cudaFuncAttributeMaxDynamicSharedMemorySize,
                             SM_TOTAL);
        cudaFuncSetAttribute(fused_nms_kernel,
                             cudaFuncAttributePreferredSharedMemoryCarveout,
                             cudaSharedmemCarveoutMaxShared);
        attr_done = true;
    }
    fused_nms_kernel<<<NBLK, NTHR, SM_TOTAL>>>(mask, (float*)d_out);
}